// round 15
// baseline (speedup 1.0000x reference)
#include <cuda_runtime.h>
#include <cuda_fp16.h>
#include <cstdint>

// ---------------------------------------------------------------------------
// R=4, B=256, N=200, NF=5, H=50, OUT=2. grid g = r*256 + b. One CTA per graph.
//
// Per graph:
//   A       = adj + I (exact in fp16: {0,1,2})
//   deg[n]  = 1 + sum_m adj[n,m];  dinv[n] = rsqrt(deg[n])
//   zd[m,f] = dinv[m] * (x @ W1)[m,f]
//   D[n,f]  = sum_m A[n,m] * zd[m,f]
//   q[m]    = dinv[m] * sum_f silu(dinv[m]*D[m,f] + b1[f]) * (W2@W3)[f]
//   t[m]    = sum_n dinv[n] * A[n,m]   (column pass, incl. patched diagonal)
//   e       = sum_m q[m] * t[m]        (order-exchanged; fp32 reassociation)
// out[b] = sum_r nu[b,r] * (e(r,b) + 200*(b2.W3 + b3))
//
// GEMM: warp-level mma.sync m16n8k16 FP16 single-pass (~3e-4 end-to-end,
// inside 1e-3). A [208x208] fp16 row-major, stride 432 B; B = zd^T fp16.
//
// R14 = R12 resubmit (infra failure, no kernel signal):
// t computed by the 6 MMA-idle warps (26..31) during Phase 4 via a
// conflict-free column pass (direct stores — R11's Phase-2 atomics were the
// regression). Phase 6 deleted; e fused into Phase 5. ldsm_x4 B-merge kept.
// ---------------------------------------------------------------------------

static constexpr int THREADS = 1024;

static constexpr int STRA = 432;                    // A row stride bytes (216 fp16)
static constexpr int STRD = 228;                    // D row stride bytes (57 f32)

static constexpr int SM_DINV = 0;                   // 256 f32
static constexpr int SM_T    = 1024;                // 208 f32 (t vector)
static constexpr int SM_X    = 2048;                // 1000 f32
static constexpr int SM_W1   = 6048;                // 250 f32
static constexpr int SM_W    = 7048;                // 50 f32 (W2@W3)
static constexpr int SM_B1   = 7248;                // 50 f32
static constexpr int SM_EP   = 7456;                // 32 f32 -> 7584
static constexpr int SM_FLAG = 7584;                // 1 int
static constexpr int SM_A    = 7616;                // 208*432 = 89856
static constexpr int SM_ZH   = SM_A  + 208 * STRA;  // 97472: 56*432 = 24192
static constexpr int SM_D    = SM_ZH + 56 * STRA;   // 121664: 208*228 = 47424
static constexpr int SM_TOTAL= SM_D  + 208 * STRD;  // 169088 bytes

__device__ float g_e[1024];          // per-graph energy
__device__ unsigned int g_ctr = 0;   // last-block counter (reset each launch)

// ---------------------------------------------------------------------------
static __device__ __forceinline__ uint32_t smem_u32(const void* p) {
    uint32_t a;
    asm("{ .reg .u64 t; cvta.to.shared.u64 t, %1; cvt.u32.u64 %0, t; }" : "=r"(a) : "l"(p));
    return a;
}
static __device__ __forceinline__ void ldsm_x4(uint32_t& r0, uint32_t& r1,
                                               uint32_t& r2, uint32_t& r3, uint32_t a) {
    asm volatile("ldmatrix.sync.aligned.m8n8.x4.shared.b16 {%0,%1,%2,%3}, [%4];"
                 : "=r"(r0), "=r"(r1), "=r"(r2), "=r"(r3) : "r"(a));
}
static __device__ __forceinline__ void ldsm_x2(uint32_t& r0, uint32_t& r1, uint32_t a) {
    asm volatile("ldmatrix.sync.aligned.m8n8.x2.shared.b16 {%0,%1}, [%2];"
                 : "=r"(r0), "=r"(r1) : "r"(a));
}
static __device__ __forceinline__ void mma16816f16(float* c,
                                                   uint32_t a0, uint32_t a1, uint32_t a2, uint32_t a3,
                                                   uint32_t b0, uint32_t b1) {
    asm volatile("mma.sync.aligned.m16n8k16.row.col.f32.f16.f16.f32 "
                 "{%0,%1,%2,%3}, {%4,%5,%6,%7}, {%8,%9}, {%0,%1,%2,%3};"
                 : "+f"(c[0]), "+f"(c[1]), "+f"(c[2]), "+f"(c[3])
                 : "r"(a0), "r"(a1), "r"(a2), "r"(a3), "r"(b0), "r"(b1));
}
static __device__ __forceinline__ float2 h2_to_f2(uint32_t pr) {
    return __half22float2(*reinterpret_cast<const __half2*>(&pr));
}

// ---------------------------------------------------------------------------
__global__ void __launch_bounds__(THREADS, 1) gnn_main(
    const float* __restrict__ x,   // [R,B,200,5]
    const int*   __restrict__ adj, // [R,B,200,200]
    const float* __restrict__ nu,  // [B,R]
    const float* __restrict__ W1,  // [5,50]
    const float* __restrict__ b1,  // [50]
    const float* __restrict__ W2,  // [50,2]
    const float* __restrict__ b2,  // [2]
    const float* __restrict__ W3,  // [2,1]
    const float* __restrict__ b3,  // [1]
    float* __restrict__ out)       // [B]
{
    extern __shared__ char smem[];
    const uint32_t sb = smem_u32(smem);
    const int tid = threadIdx.x, wid = tid >> 5, lid = tid & 31;
    const int g = blockIdx.x;

    float* dinv_s = (float*)(smem + SM_DINV);
    float* t_s    = (float*)(smem + SM_T);
    float* x_s    = (float*)(smem + SM_X);
    float* w1_s   = (float*)(smem + SM_W1);
    float* w_s    = (float*)(smem + SM_W);
    float* b1_s   = (float*)(smem + SM_B1);
    float* ep_s   = (float*)(smem + SM_EP);

    // --- Phase 0 (no sync needed before loader: all stores disjoint) -------
    {
        uint4 z; z.x = z.y = z.z = z.w = 0u;
        // A rows 0..199, cols 200..207 (bytes 400..415)
        if (tid < 200) *reinterpret_cast<uint4*>(smem + SM_A + tid * STRA + 400) = z;
        // ZH rows f=0..49, m=200..207
        if (tid < 50)  *reinterpret_cast<uint4*>(smem + SM_ZH + tid * STRA + 400) = z;
        // A rows 200..207 full (26 uint4/row * 8 rows = 208)
        if (tid >= 256 && tid < 464) {
            int i = tid - 256;
            int r = i / 26, c = i - r * 26;
            *reinterpret_cast<uint4*>(smem + SM_A + (200 + r) * STRA + c * 16) = z;
        }
        // ZH rows f=50..55 full (26 uint4/row * 6 rows = 156)
        if (tid >= 512 && tid < 668) {
            int i = tid - 512;
            int r = i / 26, c = i - r * 26;
            *reinterpret_cast<uint4*>(smem + SM_ZH + (50 + r) * STRA + c * 16) = z;
        }
    }
    {
        const float* xg = x + (size_t)g * 1000;
        if (tid < 1000) x_s[tid] = xg[tid];
        if (tid < 250)  w1_s[tid] = W1[tid];
        if (tid >= 448 && tid < 498) {
            int f = tid - 448;
            w_s[f]  = W2[f * 2] * W3[0] + W2[f * 2 + 1] * W3[1];
            b1_s[f] = b1[f];
        }
    }

    // --- Phase 1: adjacency -> fp16 rows, single batch MLP=10 per thread.
    // Flat: 10000 int4 (4 ints = 4 fp16 = 8 smem bytes).
    {
        const int4* ab = reinterpret_cast<const int4*>(adj) + (size_t)g * 10000;
        int4 v[10];
        #pragma unroll
        for (int i = 0; i < 10; ++i) {
            int idx = i * 1024 + tid;
            if (idx < 10000) v[i] = ab[idx];
            else             v[i] = make_int4(0, 0, 0, 0);
        }
        #pragma unroll
        for (int i = 0; i < 10; ++i) {
            int idx = i * 1024 + tid;
            if (idx < 10000) {
                int row = idx / 50;
                int c   = idx - row * 50;
                uint2 p;   // int 0/1 -> packed fp16x2 (0x3C00 = fp16 1.0)
                p.x = (uint32_t)v[i].x * 0x3C00u + (uint32_t)v[i].y * 0x3C000000u;
                p.y = (uint32_t)v[i].z * 0x3C00u + (uint32_t)v[i].w * 0x3C000000u;
                *reinterpret_cast<uint2*>(smem + SM_A + row * STRA + c * 8) = p;
            }
        }
    }
    __syncthreads();

    // --- Phase 2: rowsum -> dinv = rsqrt(sum+1); SAME warp patches the
    // diagonal (A[row,row] += 1) — no cross-warp race.
    {
        for (int row = wid; row < 200; row += 32) {
            const uint32_t* Ar = (const uint32_t*)(smem + SM_A + row * STRA);
            float s = 0.f;
            #pragma unroll
            for (int c = 0; c < 3; ++c) {
                float2 a2 = h2_to_f2(Ar[c * 32 + lid]);
                s += a2.x + a2.y;
            }
            if (lid < 4) {
                float2 a2 = h2_to_f2(Ar[96 + lid]);
                s += a2.x + a2.y;
            }
            #pragma unroll
            for (int o = 16; o > 0; o >>= 1) s += __shfl_down_sync(0xFFFFFFFFu, s, o);
            if (lid == 0) {
                dinv_s[row] = rsqrtf(s + 1.0f);
                __half* pp = (__half*)(smem + SM_A + row * STRA + row * 2);
                *pp = __hadd(*pp, __float2half(1.0f));   // self loop (exact)
            }
        }
    }
    __syncthreads();

    // --- Phase 3: zd^T fp16 into [f][m] rows (stride 432B)
    for (int idx = tid; idx < 5000; idx += THREADS) {
        int f  = idx / 100;
        int mp = idx - f * 100;
        int m0 = mp * 2;
        const float* xr = x_s + m0 * 5;
        float z0 = 0.f, z1 = 0.f;
        #pragma unroll
        for (int k = 0; k < 5; k++) {
            float wv = w1_s[k * 50 + f];
            z0 += xr[k] * wv;
            z1 += xr[5 + k] * wv;
        }
        z0 *= dinv_s[m0];
        z1 *= dinv_s[m0 + 1];
        __half2 hp = __floats2half2_rn(z0, z1);
        *(__half2*)(smem + SM_ZH + (uint32_t)f * STRA + (uint32_t)m0 * 2) = hp;
    }
    __syncthreads();

    // --- Phase 4: warps 0..25: D = A @ zd (26 warp-tasks, ldsm_x4 B-merge).
    //              warps 26..31: t[m] = sum_n dinv[n]*A[n,m] (column pass,
    //              hidden in the MMA shadow; diagonal already patched).
    if (wid < 26) {
        const int mt   = wid >> 1;
        const int half = wid & 1;
        const int nt0  = half * 4;
        const int ncnt = half ? 3 : 4;

        const uint32_t a_lane  = sb + SM_A + (uint32_t)(lid & 15) * STRA + (uint32_t)(lid >> 4) * 16;
        const uint32_t b_lane  = (uint32_t)(lid & 7) * STRA + (uint32_t)((lid >> 3) & 1) * 16;
        const uint32_t b_lane4 = b_lane + (uint32_t)((lid >> 4) & 1) * (8u * STRA);
        const uint32_t zbase   = sb + SM_ZH + (uint32_t)(nt0 * 8) * STRA;

        float acc[4][4];
        #pragma unroll
        for (int j = 0; j < 4; j++)
            #pragma unroll
            for (int i = 0; i < 4; i++) acc[j][i] = 0.f;

        for (int k = 0; k < 13; ++k) {
            uint32_t a0, a1, a2, a3;
            ldsm_x4(a0, a1, a2, a3, a_lane + (uint32_t)(mt * 16) * STRA + (uint32_t)k * 32);
            uint32_t bf[8];
            if (half == 0) {
                ldsm_x4(bf[0], bf[1], bf[2], bf[3], zbase + (uint32_t)k * 32 + b_lane4);
                ldsm_x4(bf[4], bf[5], bf[6], bf[7], zbase + 16u * STRA + (uint32_t)k * 32 + b_lane4);
            } else {
                ldsm_x4(bf[0], bf[1], bf[2], bf[3], zbase + (uint32_t)k * 32 + b_lane4);
                ldsm_x2(bf[4], bf[5], zbase + 16u * STRA + (uint32_t)k * 32 + b_lane);
            }
            #pragma unroll
            for (int j = 0; j < 4; ++j) {
                if (j < ncnt)
                    mma16816f16(acc[j], a0, a1, a2, a3, bf[2 * j], bf[2 * j + 1]);
            }
        }

        // store C fragments to D. STRD = 228 B is 4-mod-8 -> scalar stores only.
        #pragma unroll
        for (int j = 0; j < 4; ++j) {
            if (j < ncnt) {
                uint32_t r0 = (uint32_t)(mt * 16 + (lid >> 2));
                uint32_t c4 = (uint32_t)((nt0 + j) * 8 + (lid & 3) * 2) * 4;
                uint32_t ad0 = sb + SM_D + r0 * STRD + c4;
                asm volatile("st.shared.f32 [%0], %1;"
                             :: "r"(ad0), "f"(acc[j][0]) : "memory");
                asm volatile("st.shared.f32 [%0], %1;"
                             :: "r"(ad0 + 4u), "f"(acc[j][1]) : "memory");
                asm volatile("st.shared.f32 [%0], %1;"
                             :: "r"(ad0 + 8u * STRD), "f"(acc[j][2]) : "memory");
                asm volatile("st.shared.f32 [%0], %1;"
                             :: "r"(ad0 + 8u * STRD + 4u), "f"(acc[j][3]) : "memory");
            }
        }
    } else {
        // t column pass: 192 threads cover m = 0..191; warp 26 lanes 0..7
        // additionally cover m = 192..199. Conflict-free (16 words/iter,
        // 2 lanes broadcast per word; dinv broadcast).
        int m = (wid - 26) * 32 + lid;          // 0..191
        const char* colp = smem + SM_A + m * 2;
        float acc = 0.f;
        #pragma unroll 4
        for (int n = 0; n < 200; ++n)
            acc += dinv_s[n] * __half2float(*(const __half*)(colp + n * STRA));
        t_s[m] = acc;
        if (wid == 26 && lid < 8) {
            int m2 = 192 + lid;
            const char* colp2 = smem + SM_A + m2 * 2;
            float acc2 = 0.f;
            #pragma unroll 4
            for (int n = 0; n < 200; ++n)
                acc2 += dinv_s[n] * __half2float(*(const __half*)(colp2 + n * STRA));
            t_s[m2] = acc2;
        }
    }
    __syncthreads();

    // --- Phase 5: per-atom silu + dot(w) fused with e-contribution.
    // 4 threads per atom (13 f's each), quad reduce, contrib = q[n]*t[n],
    // warp partials to ep_s. (Old Phase 6 eliminated.)
    {
        int n    = tid >> 2;          // 0..255
        int part = tid & 3;
        float p = 0.f, dn = 0.f;
        if (n < 200) {
            dn = dinv_s[n];
            const float* Dr = (const float*)(smem + SM_D + n * STRD);
            #pragma unroll
            for (int j = 0; j < 13; ++j) {
                int f = part * 13 + j;
                if (f < 50) {
                    float h = dn * Dr[f] + b1_s[f];
                    p += (h / (1.0f + __expf(-h))) * w_s[f];
                }
            }
        }
        p += __shfl_xor_sync(0xFFFFFFFFu, p, 1);
        p += __shfl_xor_sync(0xFFFFFFFFu, p, 2);
        float contrib = (part == 0 && n < 200) ? dn * p * t_s[n] : 0.f;
        #pragma unroll
        for (int o = 16; o > 0; o >>= 1)
            contrib += __shfl_down_sync(0xFFFFFFFFu, contrib, o);
        if (lid == 0) ep_s[wid] = contrib;
    }
    __syncthreads();

    // --- Tail: publish e; last block does the deterministic combine.
    if (tid == 0) {
        float e = 0.f;
        #pragma unroll
        for (int i = 0; i < 32; i++) e += ep_s[i];
        g_e[g] = e;
        __threadfence();
        unsigned v = atomicAdd(&g_ctr, 1u);
        *(int*)(smem + SM_FLAG) = (v == (unsigned)(gridDim.x - 1)) ? 1 : 0;
    }
    __syncthreads();
    if (*(int*)(smem + SM_FLAG)) {
        if (tid == 0) g_ctr = 0;                 // reset for next graph replay
        if (tid < 256) {
            volatile const float* ge = g_e;      // peers' writes are L2-visible
            float s3 = b2[0] * W3[0] + b2[1] * W3[1] + b3[0];
            float bias = 200.0f * s3;
            int b = tid;
            float acc = 0.f;
            #pragma unroll
            for (int r = 0; r < 4; r++)
                acc += nu[b * 4 + r] * (ge[r * 256 + b] + bias);
            out[b] = acc;
        }
    }
}

// ---------------------------------------------------------------------------
extern "C" void kernel_launch(void* const* d_in, const int* in_sizes, int n_in,
                              void* d_out, int out_size) {
    const float* x   = (const float*)d_in[0];
    const int*   adj = (const int*)  d_in[1];
    const float* nu  = (const float*)d_in[2];
    const float* W1  = (const float*)d_in[3];
    const float* b1  = (const float*)d_in[4];
    const float* W2  = (const float*)d_in[5];
    const float* b2  = (const float*)d_in[6];
    const float* W3  = (const float*)d_in[7];
    const float* b3  = (const float*)d_in[8];

    cudaFuncSetAttribute(gnn_main, cudaFuncAttributeMaxDynamicSharedMemorySize, SM_TOTAL);

    gnn_main<<<1024, THREADS, SM_TOTAL>>>(x, adj, nu, W1, b1, W2, b2, W3, b3,
                                          (float*)d_out);
}

// round 16
// speedup vs baseline: 1.0770x; 1.0770x over previous
#include <cuda_runtime.h>
#include <cuda_fp16.h>
#include <cstdint>

// ---------------------------------------------------------------------------
// R=4, B=256, N=200, NF=5, H=50, OUT=2. grid g = r*256 + b. One CTA per graph.
//
// Per graph:
//   A       = adj + I (exact in fp16: {0,1,2})
//   deg[n]  = 1 + sum_m adj[n,m];  dinv[n] = rsqrt(deg[n])
//   zd[m,f] = dinv[m] * (x @ W1)[m,f]
//   D[n,f]  = sum_m A[n,m] * zd[m,f]
//   q[m]    = dinv[m] * sum_f silu(dinv[m]*D[m,f] + b1[f]) * (W2@W3)[f]
//   e       = sum_n dinv[n] * (A[n,:] . q)
// out[b] = sum_r nu[b,r] * (e(r,b) + 200*(b2.W3 + b3))
//
// GEMM: warp-level mma.sync m16n8k16 FP16 single-pass (~3e-4 end-to-end,
// inside 1e-3). A [208x208] fp16 row-major, stride 432 B; B = zd^T fp16.
//
// R16 = R10 (best: 110.9us) + ldsm_x4 B-fragment merge ONLY.
// Both t-vector variants (R11 atomics 115.2, R12 column-pass 121.3) regressed
// vs R10's plain Phase 6 — reverted. The x4 merge halves Phase-4 LDSM count
// at identical bytes; numerically validated in R11/R12 (identical rel_err).
// ---------------------------------------------------------------------------

static constexpr int THREADS = 1024;

static constexpr int STRA = 432;                    // A row stride bytes (216 fp16)
static constexpr int STRD = 228;                    // D row stride bytes (57 f32)

static constexpr int SM_DINV = 0;                   // 256 f32
static constexpr int SM_Q    = 1024;                // 256 f32
static constexpr int SM_X    = 2048;                // 1000 f32
static constexpr int SM_W1   = 6048;                // 250 f32
static constexpr int SM_W    = 7048;                // 50 f32 (W2@W3)
static constexpr int SM_B1   = 7248;                // 50 f32
static constexpr int SM_EP   = 7456;                // 32 f32 -> 7584
static constexpr int SM_FLAG = 7584;                // 1 int
static constexpr int SM_A    = 7616;                // 208*432 = 89856
static constexpr int SM_ZH   = SM_A  + 208 * STRA;  // 97472: 56*432 = 24192
static constexpr int SM_D    = SM_ZH + 56 * STRA;   // 121664: 208*228 = 47424
static constexpr int SM_TOTAL= SM_D  + 208 * STRD;  // 169088 bytes

__device__ float g_e[1024];          // per-graph energy
__device__ unsigned int g_ctr = 0;   // last-block counter (reset each launch)

// ---------------------------------------------------------------------------
static __device__ __forceinline__ uint32_t smem_u32(const void* p) {
    uint32_t a;
    asm("{ .reg .u64 t; cvta.to.shared.u64 t, %1; cvt.u32.u64 %0, t; }" : "=r"(a) : "l"(p));
    return a;
}
static __device__ __forceinline__ void ldsm_x4(uint32_t& r0, uint32_t& r1,
                                               uint32_t& r2, uint32_t& r3, uint32_t a) {
    asm volatile("ldmatrix.sync.aligned.m8n8.x4.shared.b16 {%0,%1,%2,%3}, [%4];"
                 : "=r"(r0), "=r"(r1), "=r"(r2), "=r"(r3) : "r"(a));
}
static __device__ __forceinline__ void ldsm_x2(uint32_t& r0, uint32_t& r1, uint32_t a) {
    asm volatile("ldmatrix.sync.aligned.m8n8.x2.shared.b16 {%0,%1}, [%2];"
                 : "=r"(r0), "=r"(r1) : "r"(a));
}
static __device__ __forceinline__ void mma16816f16(float* c,
                                                   uint32_t a0, uint32_t a1, uint32_t a2, uint32_t a3,
                                                   uint32_t b0, uint32_t b1) {
    asm volatile("mma.sync.aligned.m16n8k16.row.col.f32.f16.f16.f32 "
                 "{%0,%1,%2,%3}, {%4,%5,%6,%7}, {%8,%9}, {%0,%1,%2,%3};"
                 : "+f"(c[0]), "+f"(c[1]), "+f"(c[2]), "+f"(c[3])
                 : "r"(a0), "r"(a1), "r"(a2), "r"(a3), "r"(b0), "r"(b1));
}
static __device__ __forceinline__ float2 h2_to_f2(uint32_t pr) {
    return __half22float2(*reinterpret_cast<const __half2*>(&pr));
}

// ---------------------------------------------------------------------------
__global__ void __launch_bounds__(THREADS, 1) gnn_main(
    const float* __restrict__ x,   // [R,B,200,5]
    const int*   __restrict__ adj, // [R,B,200,200]
    const float* __restrict__ nu,  // [B,R]
    const float* __restrict__ W1,  // [5,50]
    const float* __restrict__ b1,  // [50]
    const float* __restrict__ W2,  // [50,2]
    const float* __restrict__ b2,  // [2]
    const float* __restrict__ W3,  // [2,1]
    const float* __restrict__ b3,  // [1]
    float* __restrict__ out)       // [B]
{
    extern __shared__ char smem[];
    const uint32_t sb = smem_u32(smem);
    const int tid = threadIdx.x, wid = tid >> 5, lid = tid & 31;
    const int g = blockIdx.x;

    float* dinv_s = (float*)(smem + SM_DINV);
    float* q_s    = (float*)(smem + SM_Q);
    float* x_s    = (float*)(smem + SM_X);
    float* w1_s   = (float*)(smem + SM_W1);
    float* w_s    = (float*)(smem + SM_W);
    float* b1_s   = (float*)(smem + SM_B1);
    float* ep_s   = (float*)(smem + SM_EP);

    // --- Phase 0 (no sync needed before loader: all stores disjoint) -------
    {
        uint4 z; z.x = z.y = z.z = z.w = 0u;
        // A rows 0..199, cols 200..207 (bytes 400..415)
        if (tid < 200) *reinterpret_cast<uint4*>(smem + SM_A + tid * STRA + 400) = z;
        // ZH rows f=0..49, m=200..207
        if (tid < 50)  *reinterpret_cast<uint4*>(smem + SM_ZH + tid * STRA + 400) = z;
        // A rows 200..207 full (26 uint4/row * 8 rows = 208)
        if (tid >= 256 && tid < 464) {
            int i = tid - 256;
            int r = i / 26, c = i - r * 26;
            *reinterpret_cast<uint4*>(smem + SM_A + (200 + r) * STRA + c * 16) = z;
        }
        // ZH rows f=50..55 full (26 uint4/row * 6 rows = 156)
        if (tid >= 512 && tid < 668) {
            int i = tid - 512;
            int r = i / 26, c = i - r * 26;
            *reinterpret_cast<uint4*>(smem + SM_ZH + (50 + r) * STRA + c * 16) = z;
        }
    }
    {
        const float* xg = x + (size_t)g * 1000;
        if (tid < 1000) x_s[tid] = xg[tid];
        if (tid < 250)  w1_s[tid] = W1[tid];
        if (tid >= 448 && tid < 498) {
            int f = tid - 448;
            w_s[f]  = W2[f * 2] * W3[0] + W2[f * 2 + 1] * W3[1];
            b1_s[f] = b1[f];
        }
    }

    // --- Phase 1: adjacency -> fp16 rows, single batch MLP=10 per thread.
    // Flat: 10000 int4 (4 ints = 4 fp16 = 8 smem bytes).
    {
        const int4* ab = reinterpret_cast<const int4*>(adj) + (size_t)g * 10000;
        int4 v[10];
        #pragma unroll
        for (int i = 0; i < 10; ++i) {
            int idx = i * 1024 + tid;
            if (idx < 10000) v[i] = ab[idx];
            else             v[i] = make_int4(0, 0, 0, 0);
        }
        #pragma unroll
        for (int i = 0; i < 10; ++i) {
            int idx = i * 1024 + tid;
            if (idx < 10000) {
                int row = idx / 50;
                int c   = idx - row * 50;
                uint2 p;   // int 0/1 -> packed fp16x2 (0x3C00 = fp16 1.0)
                p.x = (uint32_t)v[i].x * 0x3C00u + (uint32_t)v[i].y * 0x3C000000u;
                p.y = (uint32_t)v[i].z * 0x3C00u + (uint32_t)v[i].w * 0x3C000000u;
                *reinterpret_cast<uint2*>(smem + SM_A + row * STRA + c * 8) = p;
            }
        }
    }
    __syncthreads();

    // --- Phase 2: rowsum -> dinv = rsqrt(sum+1); SAME warp patches the
    // diagonal (A[row,row] += 1) — no cross-warp race.
    {
        for (int row = wid; row < 200; row += 32) {
            const uint32_t* Ar = (const uint32_t*)(smem + SM_A + row * STRA);
            float s = 0.f;
            #pragma unroll
            for (int c = 0; c < 3; ++c) {
                float2 a2 = h2_to_f2(Ar[c * 32 + lid]);
                s += a2.x + a2.y;
            }
            if (lid < 4) {
                float2 a2 = h2_to_f2(Ar[96 + lid]);
                s += a2.x + a2.y;
            }
            #pragma unroll
            for (int o = 16; o > 0; o >>= 1) s += __shfl_down_sync(0xFFFFFFFFu, s, o);
            if (lid == 0) {
                dinv_s[row] = rsqrtf(s + 1.0f);
                __half* pp = (__half*)(smem + SM_A + row * STRA + row * 2);
                *pp = __hadd(*pp, __float2half(1.0f));   // self loop (exact)
            }
        }
    }
    __syncthreads();

    // --- Phase 3: zd^T fp16 into [f][m] rows (stride 432B)
    for (int idx = tid; idx < 5000; idx += THREADS) {
        int f  = idx / 100;
        int mp = idx - f * 100;
        int m0 = mp * 2;
        const float* xr = x_s + m0 * 5;
        float z0 = 0.f, z1 = 0.f;
        #pragma unroll
        for (int k = 0; k < 5; k++) {
            float wv = w1_s[k * 50 + f];
            z0 += xr[k] * wv;
            z1 += xr[5 + k] * wv;
        }
        z0 *= dinv_s[m0];
        z1 *= dinv_s[m0 + 1];
        __half2 hp = __floats2half2_rn(z0, z1);
        *(__half2*)(smem + SM_ZH + (uint32_t)f * STRA + (uint32_t)m0 * 2) = hp;
    }
    __syncthreads();

    // --- Phase 4: D = A @ zd via fp16 mma.sync. 26 warp-tasks:
    // wid 0..25: mt = wid>>1, half = wid&1 (nt 0..3 / 4..6).
    // B fragments via ldsm_x4 nt-pairs (half the LDSM instructions).
    if (wid < 26) {
        const int mt   = wid >> 1;
        const int half = wid & 1;
        const int nt0  = half * 4;
        const int ncnt = half ? 3 : 4;

        const uint32_t a_lane  = sb + SM_A + (uint32_t)(lid & 15) * STRA + (uint32_t)(lid >> 4) * 16;
        const uint32_t b_lane  = (uint32_t)(lid & 7) * STRA + (uint32_t)((lid >> 3) & 1) * 16;
        const uint32_t b_lane4 = b_lane + (uint32_t)((lid >> 4) & 1) * (8u * STRA);
        const uint32_t zbase   = sb + SM_ZH + (uint32_t)(nt0 * 8) * STRA;

        float acc[4][4];
        #pragma unroll
        for (int j = 0; j < 4; j++)
            #pragma unroll
            for (int i = 0; i < 4; i++) acc[j][i] = 0.f;

        for (int k = 0; k < 13; ++k) {
            uint32_t a0, a1, a2, a3;
            ldsm_x4(a0, a1, a2, a3, a_lane + (uint32_t)(mt * 16) * STRA + (uint32_t)k * 32);
            uint32_t bf[8];
            if (half == 0) {
                ldsm_x4(bf[0], bf[1], bf[2], bf[3], zbase + (uint32_t)k * 32 + b_lane4);
                ldsm_x4(bf[4], bf[5], bf[6], bf[7], zbase + 16u * STRA + (uint32_t)k * 32 + b_lane4);
            } else {
                ldsm_x4(bf[0], bf[1], bf[2], bf[3], zbase + (uint32_t)k * 32 + b_lane4);
                ldsm_x2(bf[4], bf[5], zbase + 16u * STRA + (uint32_t)k * 32 + b_lane);
            }
            #pragma unroll
            for (int j = 0; j < 4; ++j) {
                if (j < ncnt)
                    mma16816f16(acc[j], a0, a1, a2, a3, bf[2 * j], bf[2 * j + 1]);
            }
        }

        // store C fragments to D. STRD = 228 B is 4-mod-8 -> scalar stores only.
        #pragma unroll
        for (int j = 0; j < 4; ++j) {
            if (j < ncnt) {
                uint32_t r0 = (uint32_t)(mt * 16 + (lid >> 2));
                uint32_t c4 = (uint32_t)((nt0 + j) * 8 + (lid & 3) * 2) * 4;
                uint32_t ad0 = sb + SM_D + r0 * STRD + c4;
                asm volatile("st.shared.f32 [%0], %1;"
                             :: "r"(ad0), "f"(acc[j][0]) : "memory");
                asm volatile("st.shared.f32 [%0], %1;"
                             :: "r"(ad0 + 4u), "f"(acc[j][1]) : "memory");
                asm volatile("st.shared.f32 [%0], %1;"
                             :: "r"(ad0 + 8u * STRD), "f"(acc[j][2]) : "memory");
                asm volatile("st.shared.f32 [%0], %1;"
                             :: "r"(ad0 + 8u * STRD + 4u), "f"(acc[j][3]) : "memory");
            }
        }
    }
    __syncthreads();

    // --- Phase 5: per-atom silu + dot(w); 4 threads per atom (13 f's each),
    // quad shuffle-reduce. q[n] = dinv[n]*p[n]; q = 0 for pad atoms.
    {
        int n    = tid >> 2;          // 0..255
        int part = tid & 3;
        float p = 0.f;
        float dn = (n < 200) ? dinv_s[n] : 0.f;
        if (n < 200) {
            const float* Dr = (const float*)(smem + SM_D + n * STRD);
            #pragma unroll
            for (int j = 0; j < 13; ++j) {
                int f = part * 13 + j;
                if (f < 50) {
                    float h = dn * Dr[f] + b1_s[f];
                    p += (h / (1.0f + __expf(-h))) * w_s[f];
                }
            }
        }
        p += __shfl_xor_sync(0xFFFFFFFFu, p, 1);
        p += __shfl_xor_sync(0xFFFFFFFFu, p, 2);
        if (part == 0) q_s[n] = dn * p;   // 0 for n >= 200
    }
    __syncthreads();

    // --- Phase 6: e = sum_n dinv[n] * (A[n,:] . q)
    {
        float my = 0.f;
        for (int n = wid; n < 200; n += 32) {
            const char* Ar = smem + SM_A + n * STRA;
            float acc2 = 0.f;
            #pragma unroll
            for (int c = 0; c < 3; ++c) {       // m = 0..191
                float2 a2 = h2_to_f2(*(const uint32_t*)(Ar + c * 128 + lid * 4));
                float2 qq = *(const float2*)(smem + SM_Q + (c * 64 + lid * 2) * 4);
                acc2 += a2.x * qq.x + a2.y * qq.y;
            }
            if (lid < 8) {                       // m = 192..207 (pads zero)
                float2 a2 = h2_to_f2(*(const uint32_t*)(Ar + 384 + lid * 4));
                float2 qq = *(const float2*)(smem + SM_Q + (192 + lid * 2) * 4);
                acc2 += a2.x * qq.x + a2.y * qq.y;
            }
            #pragma unroll
            for (int o = 16; o > 0; o >>= 1) acc2 += __shfl_down_sync(0xFFFFFFFFu, acc2, o);
            if (lid == 0) my += dinv_s[n] * acc2;
        }
        if (lid == 0) ep_s[wid] = my;
    }
    __syncthreads();

    // --- Tail: publish e; last block does the deterministic combine.
    if (tid == 0) {
        float e = 0.f;
        #pragma unroll
        for (int i = 0; i < 32; i++) e += ep_s[i];
        g_e[g] = e;
        __threadfence();
        unsigned v = atomicAdd(&g_ctr, 1u);
        *(int*)(smem + SM_FLAG) = (v == (unsigned)(gridDim.x - 1)) ? 1 : 0;
    }
    __syncthreads();
    if (*(int*)(smem + SM_FLAG)) {
        if (tid == 0) g_ctr = 0;                 // reset for next graph replay
        if (tid < 256) {
            volatile const float* ge = g_e;      // peers' writes are L2-visible
            float s3 = b2[0] * W3[0] + b2[1] * W3[1] + b3[0];
            float bias = 200.0f * s3;
            int b = tid;
            float acc = 0.f;
            #pragma unroll
            for (int r = 0; r < 4; r++)
                acc += nu[b * 4 + r] * (ge[r * 256 + b] + bias);
            out[b] = acc;
        }
    }
}

// ---------------------------------------------------------------------------
extern "C" void kernel_launch(void* const* d_in, const int* in_sizes, int n_in,
                              void* d_out, int out_size) {
    const float* x   = (const float*)d_in[0];
    const int*   adj = (const int*)  d_in[1];
    const float* nu  = (const float*)d_in[2];
    const float* W1  = (const float*)d_in[3];
    const float* b1  = (const float*)d_in[4];
    const float* W2  = (const float*)d_in[5];
    const float* b2  = (const float*)d_in[6];
    const float* W3  = (const float*)d_in[7];
    const float* b3  = (const float*)d_in[8];

    cudaFuncSetAttribute(gnn_main, cudaFuncAttributeMaxDynamicSharedMemorySize, SM_TOTAL);

    gnn_main<<<1024, THREADS, SM_TOTAL>>>(x, adj, nu, W1, b1, W2, b2, W3, b3,
                                          (float*)d_out);
}

// round 17
// speedup vs baseline: 1.3462x; 1.2500x over previous
#include <cuda_runtime.h>
#include <cuda_fp16.h>
#include <cstdint>

// ---------------------------------------------------------------------------
// R=4, B=256, N=200, NF=5, H=50, OUT=2. grid g = r*256 + b. One CTA per graph,
// 512 threads, TWO CTAs resident per SM (smem squeezed under the 2-CTA limit).
//
// Per graph:
//   A       = adj + I (exact in fp16: {0,1,2})
//   deg[n]  = 1 + sum_m adj[n,m];  dinv[n] = rsqrt(deg[n])
//   zd[m,f] = dinv[m] * (x @ W1)[m,f]        (x staged fp16)
//   D[n,f]  = sum_m A[n,m] * zd[m,f]         (REGISTER-RESIDENT: never stored)
//   q[n]    = dinv[n] * sum_f silu(dinv[n]*D[n,f] + b1[f]) * (W2@W3)[f]
//   e       = sum_n dinv[n] * (A[n,:] . q)
// out[b] = sum_r nu[b,r] * (e(r,b) + 200*(b2.W3 + b3))
//
// R17: 2-CTA/SM redesign.
//  - Phase 4: 13 warps, warp = 1 M-tile x ALL 7 N-tiles -> epilogue is
//    warp-local on the C fragments (D matrix eliminated, 47KB smem + ~150KB
//    wavefronts gone; A-fragment traffic halved).
//  - M overlap-tile: mt12 = rows 184..199 (rows 184..191 duplicated, benign
//    same-value q writes) -> A = 200 rows = 86.4KB.
//  - N overlap-tile: nt6 = f 42..49 with f<48 zero-weighted -> ZH = 50 rows.
//  - q aliases dead ZH; x staged fp16. smem = 112,480 B.
// ---------------------------------------------------------------------------

static constexpr int THREADS = 512;

static constexpr int STRA = 432;                    // A/ZH row stride bytes

static constexpr int SM_DINV = 0;                   // 208 f32 (200 used)
static constexpr int SM_W    = 832;                 // 50 f32 (W2@W3)
static constexpr int SM_B1   = 1032;                // 50 f32
static constexpr int SM_EP   = 1232;                // 16 f32
static constexpr int SM_FLAG = 1296;                // 1 int
static constexpr int SM_XH   = 1408;                // 1000 fp16 = 2000 B
static constexpr int SM_W1   = 3408;                // 250 f32 = 1000 B
static constexpr int SM_A    = 4480;                // 200*432 = 86400 (128-al)
static constexpr int SM_ZH   = SM_A + 200 * STRA;   // 90880: 50*432 = 21600
static constexpr int SM_Q    = SM_ZH;               // alias (832 B) after MMA
static constexpr int SM_TOTAL= SM_ZH + 50 * STRA;   // 112480 bytes

__device__ float g_e[1024];          // per-graph energy
__device__ unsigned int g_ctr = 0;   // last-block counter (reset each launch)

// ---------------------------------------------------------------------------
static __device__ __forceinline__ uint32_t smem_u32(const void* p) {
    uint32_t a;
    asm("{ .reg .u64 t; cvta.to.shared.u64 t, %1; cvt.u32.u64 %0, t; }" : "=r"(a) : "l"(p));
    return a;
}
static __device__ __forceinline__ void ldsm_x4(uint32_t& r0, uint32_t& r1,
                                               uint32_t& r2, uint32_t& r3, uint32_t a) {
    asm volatile("ldmatrix.sync.aligned.m8n8.x4.shared.b16 {%0,%1,%2,%3}, [%4];"
                 : "=r"(r0), "=r"(r1), "=r"(r2), "=r"(r3) : "r"(a));
}
static __device__ __forceinline__ void ldsm_x2(uint32_t& r0, uint32_t& r1, uint32_t a) {
    asm volatile("ldmatrix.sync.aligned.m8n8.x2.shared.b16 {%0,%1}, [%2];"
                 : "=r"(r0), "=r"(r1) : "r"(a));
}
static __device__ __forceinline__ void mma16816f16(float* c,
                                                   uint32_t a0, uint32_t a1, uint32_t a2, uint32_t a3,
                                                   uint32_t b0, uint32_t b1) {
    asm volatile("mma.sync.aligned.m16n8k16.row.col.f32.f16.f16.f32 "
                 "{%0,%1,%2,%3}, {%4,%5,%6,%7}, {%8,%9}, {%0,%1,%2,%3};"
                 : "+f"(c[0]), "+f"(c[1]), "+f"(c[2]), "+f"(c[3])
                 : "r"(a0), "r"(a1), "r"(a2), "r"(a3), "r"(b0), "r"(b1));
}
static __device__ __forceinline__ float2 h2_to_f2(uint32_t pr) {
    return __half22float2(*reinterpret_cast<const __half2*>(&pr));
}
static __device__ __forceinline__ float silu(float h) {
    return h / (1.0f + __expf(-h));
}

// ---------------------------------------------------------------------------
__global__ void __launch_bounds__(THREADS, 2) gnn_main(
    const float* __restrict__ x,   // [R,B,200,5]
    const int*   __restrict__ adj, // [R,B,200,200]
    const float* __restrict__ nu,  // [B,R]
    const float* __restrict__ W1,  // [5,50]
    const float* __restrict__ b1,  // [50]
    const float* __restrict__ W2,  // [50,2]
    const float* __restrict__ b2,  // [2]
    const float* __restrict__ W3,  // [2,1]
    const float* __restrict__ b3,  // [1]
    float* __restrict__ out)       // [B]
{
    extern __shared__ char smem[];
    const uint32_t sb = smem_u32(smem);
    const int tid = threadIdx.x, wid = tid >> 5, lid = tid & 31;
    const int g = blockIdx.x;

    float*  dinv_s = (float*)(smem + SM_DINV);
    float*  w_s    = (float*)(smem + SM_W);
    float*  b1_s   = (float*)(smem + SM_B1);
    float*  ep_s   = (float*)(smem + SM_EP);
    __half* xh_s   = (__half*)(smem + SM_XH);
    float*  w1_s   = (float*)(smem + SM_W1);
    float*  q_s    = (float*)(smem + SM_Q);     // aliases ZH (valid post-MMA)

    // --- Phase 0: pad zeroing + staging (disjoint from loader stores) ------
    {
        uint4 z; z.x = z.y = z.z = z.w = 0u;
        if (tid < 200) *reinterpret_cast<uint4*>(smem + SM_A + tid * STRA + 400) = z;
        if (tid < 50)  *reinterpret_cast<uint4*>(smem + SM_ZH + tid * STRA + 400) = z;
    }
    {
        const float* xg = x + (size_t)g * 1000;
        for (int i = tid; i < 1000; i += THREADS) xh_s[i] = __float2half(xg[i]);
        if (tid < 250) w1_s[tid] = W1[tid];
        if (tid >= 256 && tid < 306) {
            int f = tid - 256;
            w_s[f]  = W2[f * 2] * W3[0] + W2[f * 2 + 1] * W3[1];
            b1_s[f] = b1[f];
        }
    }

    // --- Phase 1: adjacency -> fp16 rows; 2 batches of MLP=10 per thread.
    {
        const int4* ab = reinterpret_cast<const int4*>(adj) + (size_t)g * 10000;
        #pragma unroll 1
        for (int base = 0; base < 10000; base += 5120) {
            int4 v[10];
            #pragma unroll
            for (int i = 0; i < 10; ++i) {
                int idx = base + i * 512 + tid;
                if (idx < 10000) v[i] = ab[idx];
                else             v[i] = make_int4(0, 0, 0, 0);
            }
            #pragma unroll
            for (int i = 0; i < 10; ++i) {
                int idx = base + i * 512 + tid;
                if (idx < 10000) {
                    int row = idx / 50;
                    int c   = idx - row * 50;
                    uint2 p;   // int 0/1 -> packed fp16x2 (0x3C00 = fp16 1.0)
                    p.x = (uint32_t)v[i].x * 0x3C00u + (uint32_t)v[i].y * 0x3C000000u;
                    p.y = (uint32_t)v[i].z * 0x3C00u + (uint32_t)v[i].w * 0x3C000000u;
                    *reinterpret_cast<uint2*>(smem + SM_A + row * STRA + c * 8) = p;
                }
            }
        }
    }
    __syncthreads();

    // --- Phase 2: rowsum -> dinv = rsqrt(sum+1); same warp patches diagonal.
    {
        for (int row = wid; row < 200; row += 16) {
            const uint32_t* Ar = (const uint32_t*)(smem + SM_A + row * STRA);
            float s = 0.f;
            #pragma unroll
            for (int c = 0; c < 3; ++c) {
                float2 a2 = h2_to_f2(Ar[c * 32 + lid]);
                s += a2.x + a2.y;
            }
            if (lid < 4) {
                float2 a2 = h2_to_f2(Ar[96 + lid]);
                s += a2.x + a2.y;
            }
            #pragma unroll
            for (int o = 16; o > 0; o >>= 1) s += __shfl_down_sync(0xFFFFFFFFu, s, o);
            if (lid == 0) {
                dinv_s[row] = rsqrtf(s + 1.0f);
                __half* pp = (__half*)(smem + SM_A + row * STRA + row * 2);
                *pp = __hadd(*pp, __float2half(1.0f));   // self loop (exact)
            }
        }
    }
    __syncthreads();

    // --- Phase 3: zd^T fp16 into ZH [f][m] rows (f = 0..49)
    for (int idx = tid; idx < 5000; idx += THREADS) {
        int f  = idx / 100;
        int mp = idx - f * 100;
        int m0 = mp * 2;
        const __half* xr = xh_s + m0 * 5;
        float z0 = 0.f, z1 = 0.f;
        #pragma unroll
        for (int k = 0; k < 5; k++) {
            float wv = w1_s[k * 50 + f];
            z0 += __half2float(xr[k]) * wv;
            z1 += __half2float(xr[5 + k]) * wv;
        }
        z0 *= dinv_s[m0];
        z1 *= dinv_s[m0 + 1];
        __half2 hp = __floats2half2_rn(z0, z1);
        *(__half2*)(smem + SM_ZH + (uint32_t)f * STRA + (uint32_t)m0 * 2) = hp;
    }
    __syncthreads();

    // --- Phase 4a: MMA. 13 warps; warp w = M-tile w covering ALL 7 N-tiles.
    // mt 0..11 -> rows mt*16..+15; mt 12 -> rows 184..199 (overlap, benign).
    // nt 0..5 -> f = nt*8..+7; nt 6 -> f = 42..49 (overlap, zero-weighted).
    float acc[7][4];
    int rowbase = 0;
    if (wid < 13) {
        rowbase = (wid < 12) ? wid * 16 : 184;
        const uint32_t a_lane = sb + SM_A + (uint32_t)rowbase * STRA
                              + (uint32_t)(lid & 15) * STRA + (uint32_t)(lid >> 4) * 16;
        const uint32_t b_lane = (uint32_t)(lid & 7) * STRA + (uint32_t)((lid >> 3) & 1) * 16;

        #pragma unroll
        for (int nt = 0; nt < 7; nt++)
            #pragma unroll
            for (int i = 0; i < 4; i++) acc[nt][i] = 0.f;

        for (int k = 0; k < 13; ++k) {
            uint32_t a0, a1, a2, a3;
            ldsm_x4(a0, a1, a2, a3, a_lane + (uint32_t)k * 32);
            #pragma unroll
            for (int nt = 0; nt < 7; ++nt) {
                const uint32_t zoff = (uint32_t)((nt < 6) ? nt * 8 : 42) * STRA;
                uint32_t b0, b1r;
                ldsm_x2(b0, b1r, sb + SM_ZH + zoff + (uint32_t)k * 32 + b_lane);
                mma16816f16(acc[nt], a0, a1, a2, a3, b0, b1r);
            }
        }
    }
    __syncthreads();   // all ZH reads done before q overwrites ZH (alias)

    // --- Phase 4b: register epilogue — silu + dot(w) on the C fragments.
    if (wid < 13) {
        int r0 = rowbase + (lid >> 2);
        int r1 = r0 + 8;
        float dn0 = dinv_s[r0], dn1 = dinv_s[r1];
        float p0 = 0.f, p1 = 0.f;
        #pragma unroll
        for (int nt = 0; nt < 7; ++nt) {
            int f0 = ((nt < 6) ? nt * 8 : 42) + (lid & 3) * 2;
            float w0 = w_s[f0], w1v = w_s[f0 + 1];
            if (nt == 6) {                 // zero duplicated f 42..47
                if (f0 < 48)     w0  = 0.f;
                if (f0 + 1 < 48) w1v = 0.f;
            }
            float b0v = b1_s[f0], b1vv = b1_s[f0 + 1];
            p0 += silu(fmaf(dn0, acc[nt][0], b0v))  * w0;
            p0 += silu(fmaf(dn0, acc[nt][1], b1vv)) * w1v;
            p1 += silu(fmaf(dn1, acc[nt][2], b0v))  * w0;
            p1 += silu(fmaf(dn1, acc[nt][3], b1vv)) * w1v;
        }
        p0 += __shfl_xor_sync(0xFFFFFFFFu, p0, 1);
        p0 += __shfl_xor_sync(0xFFFFFFFFu, p0, 2);
        p1 += __shfl_xor_sync(0xFFFFFFFFu, p1, 1);
        p1 += __shfl_xor_sync(0xFFFFFFFFu, p1, 2);
        if ((lid & 3) == 0) {              // duplicated rows: same-value writes
            q_s[r0] = dn0 * p0;
            q_s[r1] = dn1 * p1;
        }
    }
    __syncthreads();

    // --- Phase 6: e = sum_n dinv[n] * (A[n,:] . q)   (q[200..] never read)
    {
        float my = 0.f;
        for (int n = wid; n < 200; n += 16) {
            const char* Ar = smem + SM_A + n * STRA;
            float acc2 = 0.f;
            #pragma unroll
            for (int c = 0; c < 3; ++c) {       // m = 0..191
                float2 a2 = h2_to_f2(*(const uint32_t*)(Ar + c * 128 + lid * 4));
                float2 qq = *(const float2*)(smem + SM_Q + (c * 64 + lid * 2) * 4);
                acc2 += a2.x * qq.x + a2.y * qq.y;
            }
            if (lid < 4) {                       // m = 192..199
                float2 a2 = h2_to_f2(*(const uint32_t*)(Ar + 384 + lid * 4));
                float2 qq = *(const float2*)(smem + SM_Q + (192 + lid * 2) * 4);
                acc2 += a2.x * qq.x + a2.y * qq.y;
            }
            #pragma unroll
            for (int o = 16; o > 0; o >>= 1) acc2 += __shfl_down_sync(0xFFFFFFFFu, acc2, o);
            if (lid == 0) my += dinv_s[n] * acc2;
        }
        if (lid == 0) ep_s[wid] = my;
    }
    __syncthreads();

    // --- Tail: publish e; last block does the deterministic combine.
    if (tid == 0) {
        float e = 0.f;
        #pragma unroll
        for (int i = 0; i < 16; i++) e += ep_s[i];
        g_e[g] = e;
        __threadfence();
        unsigned v = atomicAdd(&g_ctr, 1u);
        *(int*)(smem + SM_FLAG) = (v == (unsigned)(gridDim.x - 1)) ? 1 : 0;
    }
    __syncthreads();
    if (*(int*)(smem + SM_FLAG)) {
        if (tid == 0) g_ctr = 0;                 // reset for next graph replay
        if (tid < 256) {
            volatile const float* ge = g_e;      // peers' writes are L2-visible
            float s3 = b2[0] * W3[0] + b2[1] * W3[1] + b3[0];
            float bias = 200.0f * s3;
            int b = tid;
            float acc2 = 0.f;
            #pragma unroll
            for (int r = 0; r < 4; r++)
                acc2 += nu[b * 4 + r] * (ge[r * 256 + b] + bias);
            out[b] = acc2;
        }
    }
}

// ---------------------------------------------------------------------------
extern "C" void kernel_launch(void* const* d_in, const int* in_sizes, int n_in,
                              void* d_out, int out_size) {
    const float* x   = (const float*)d_in[0];
    const int*   adj = (const int*)  d_in[1];
    const float* nu  = (const float*)d_in[2];
    const float* W1  = (const float*)d_in[3];
    const float* b1  = (const float*)d_in[4];
    const float* W2  = (const float*)d_in[5];
    const float* b2  = (const float*)d_in[6];
    const float* W3  = (const float*)d_in[7];
    const float* b3  = (const float*)d_in[8];

    cudaFuncSetAttribute(gnn_main, cudaFuncAttributeMaxDynamicSharedMemorySize, SM_TOTAL);

    gnn_main<<<1024, THREADS, SM_TOTAL>>>(x, adj, nu, W1, b1, W2, b2, W3, b3,
                                          (float*)d_out);
}